// round 3
// baseline (speedup 1.0000x reference)
#include <cuda_runtime.h>
#include <cuda_bf16.h>

// Shapes for LabelSmoothingCTCLoss: T=1024, B=128, C=256, L=64
#define T_DIM 1024
#define B_DIM 128
#define C_DIM 256
#define L_DIM 64
#define S_DIM 129          // 2*L+1
#define NTHR  128
#define PF    8            // prefetch depth (time steps)
#define NEGV  (-1.0e30f)
#define LOG2E 1.4426950408889634f
#define LN2   0.6931471805599453f

// Deterministic cross-block reduction scratch (static device arrays: no allocs)
__device__ float g_nll[B_DIM];
__device__ float g_ent[B_DIM];

__device__ __forceinline__ float ex2(float x) {
    float y; asm("ex2.approx.ftz.f32 %0, %1;" : "=f"(y) : "f"(x)); return y;
}
__device__ __forceinline__ float lg2(float x) {
    float y; asm("lg2.approx.ftz.f32 %0, %1;" : "=f"(y) : "f"(x)); return y;
}

// One block per batch element. Fused: entropy accumulation + CTC forward DP,
// reading each 1KB log_probs row exactly once.
__global__ void __launch_bounds__(NTHR, 1) ctc_fused(
    const float* __restrict__ lp,      // [T, B, C]
    const int*   __restrict__ targets, // [B, L]
    const int*   __restrict__ in_len,  // [B]
    const int*   __restrict__ tgt_len) // [B]
{
    __shared__ float lp2_sh[2][C_DIM];    // log2-domain row, double-buffered
    __shared__ float A[2][S_DIM + 2];     // alpha (log2 domain), 2 leading pads
    __shared__ float entw[NTHR / 32];

    const int b   = blockIdx.x;
    const int tid = threadIdx.x;
    const int len = __ldg(&in_len[b]);
    const int TL  = __ldg(&tgt_len[b]);

    // Static per-thread DP config: thread tid owns state s = tid
    // (thread 0 additionally owns state 128, which is always a blank).
    int  myext;
    bool allow;
    if (tid & 1) {
        const int i = tid >> 1;                  // (s-1)/2
        myext = __ldg(&targets[b * L_DIM + i]);
        allow = (tid >= 3) && (myext != __ldg(&targets[b * L_DIM + i - 1]));
    } else {
        myext = 0;          // blank
        allow = false;
    }

    if (tid < 2) { A[0][tid] = NEGV; A[1][tid] = NEGV; }  // pads, never rewritten

    const float*  row  = lp + (size_t)b * C_DIM + tid;
    const size_t  tstr = (size_t)B_DIM * C_DIM;

    // Prefetch ring: depth PF time steps, 2 columns per thread (tid, tid+128)
    float pf0[PF], pf1[PF];
#pragma unroll
    for (int j = 0; j < PF; ++j) {
        pf0[j] = __ldg(&row[(size_t)j * tstr]);
        pf1[j] = __ldg(&row[(size_t)j * tstr + 128]);
    }

    float ent = 0.f;   // per-thread sum of p*log p (natural log)
    float nll = 0.f;   // valid on thread 0 after recording

    for (int t0 = 0; t0 < T_DIM; t0 += PF) {
#pragma unroll
        for (int j = 0; j < PF; ++j) {
            const int t  = t0 + j;
            const int pb = t & 1;   // producer/read buffer parity for this step
            const float c0 = pf0[j];
            const float c1 = pf1[j];
            if (t + PF < T_DIM) {
                pf0[j] = __ldg(&row[(size_t)(t + PF) * tstr]);
                pf1[j] = __ldg(&row[(size_t)(t + PF) * tstr + 128]);
            }

            // Producer: publish log2-domain row; accumulate entropy (p*lp)
            const float d0 = c0 * LOG2E;
            const float d1 = c1 * LOG2E;
            lp2_sh[pb][tid]       = d0;
            lp2_sh[pb][tid + 128] = d1;
            ent = fmaf(ex2(d0), c0, ent);
            ent = fmaf(ex2(d1), c1, ent);
            __syncthreads();

            // Record log-likelihood when alpha of step (len-1) is available.
            // A[pb] holds alpha after step t-1.
            if (tid == 0 && t == len) {
                const float x1 = A[pb][2 * TL + 2];   // state 2*TL
                const float x0 = A[pb][2 * TL + 1];   // state 2*TL-1
                const float m  = fmaxf(x1, x0);
                const float l2 = m + lg2(ex2(x1 - m) + ex2(x0 - m));
                const float v  = -l2 * LN2;
                nll = (v > 1e29f) ? 0.f : v;          // zero_infinity
            }

            // DP update: read A[pb] (prev), write A[pb^1] (cur)
            const int rb = pb, wb = pb ^ 1;
            const float pe = lp2_sh[pb][myext];
            const float a2 = allow ? A[rb][tid] : NEGV;     // state s-2
            const float a1 = A[rb][tid + 1];                // state s-1
            const float a0 = A[rb][tid + 2];                // state s
            float v;
            if (t == 0) {
                v = (tid < 2) ? pe : NEGV;
            } else {
                const float m = fmaxf(a0, fmaxf(a1, a2));
                const float e = ex2(a0 - m) + ex2(a1 - m) + ex2(a2 - m);
                v = m + lg2(e) + pe;
            }
            A[wb][tid + 2] = v;

            if (tid == 0) {
                // Extra state 128 (final blank): from states 127,128; no skip
                float u;
                if (t == 0) {
                    u = NEGV;
                } else {
                    const float y1 = A[rb][129];            // state 127
                    const float y0 = A[rb][130];            // state 128
                    const float m  = fmaxf(y0, y1);
                    const float e  = ex2(y0 - m) + ex2(y1 - m);
                    u = m + lg2(e) + lp2_sh[pb][0];
                }
                A[wb][130] = u;
            }
        }
    }
    __syncthreads();

    // Handle len == T (alpha after step T-1 sits in A[T&1] == A[0])
    if (tid == 0 && len == T_DIM) {
        const int rb = T_DIM & 1;  // 0
        const float x1 = A[rb][2 * TL + 2];
        const float x0 = A[rb][2 * TL + 1];
        const float m  = fmaxf(x1, x0);
        const float l2 = m + lg2(ex2(x1 - m) + ex2(x0 - m));
        const float v  = -l2 * LN2;
        nll = (v > 1e29f) ? 0.f : v;
    }

    // Block-level entropy reduction (deterministic)
    float e = ent;
#pragma unroll
    for (int off = 16; off; off >>= 1)
        e += __shfl_xor_sync(0xffffffffu, e, off);
    if ((tid & 31) == 0) entw[tid >> 5] = e;
    __syncthreads();
    if (tid == 0) {
        g_ent[b] = entw[0] + entw[1] + entw[2] + entw[3];
        g_nll[b] = nll;
    }
}

__global__ void ctc_finalize(float* __restrict__ out) {
    const int tid = threadIdx.x;  // 32 threads
    float sn = 0.f, se = 0.f;
#pragma unroll
    for (int j = 0; j < 4; ++j) {
        sn += g_nll[tid * 4 + j];
        se += g_ent[tid * 4 + j];
    }
#pragma unroll
    for (int off = 16; off; off >>= 1) {
        sn += __shfl_xor_sync(0xffffffffu, sn, off);
        se += __shfl_xor_sync(0xffffffffu, se, off);
    }
    if (tid == 0) {
        // loss = 0.9 * mean_b(nll) + 0.1 * (sum p*lp) / (T*B)
        out[0] = 0.9f * (sn * (1.0f / (float)B_DIM))
               + 0.1f * (se * (1.0f / ((float)T_DIM * (float)B_DIM)));
    }
}

extern "C" void kernel_launch(void* const* d_in, const int* in_sizes, int n_in,
                              void* d_out, int out_size) {
    const float* lp = (const float*)d_in[0];
    const int*   tg = (const int*)d_in[1];
    const int*   il = (const int*)d_in[2];
    const int*   tl = (const int*)d_in[3];
    (void)in_sizes; (void)n_in; (void)out_size;

    ctc_fused<<<B_DIM, NTHR>>>(lp, tg, il, tl);
    ctc_finalize<<<1, 32>>>((float*)d_out);
}

// round 7
// speedup vs baseline: 1.7800x; 1.7800x over previous
#include <cuda_runtime.h>
#include <cuda_bf16.h>

// Shapes: T=1024, B=128, C=256, L=64, S=129
#define T_DIM 1024
#define B_DIM 128
#define C_DIM 256
#define L_DIM 64
#define NTHR  256
#define PF    8
#define LOG2E 1.4426950408889634f
#define LN2   0.6931471805599453f
#define ESENT (-1000000)

__device__ float g_nll[B_DIM];
__device__ float g_ent[B_DIM];

__device__ __forceinline__ float ex2f(float x) {
    float y; asm("ex2.approx.ftz.f32 %0, %1;" : "=f"(y) : "f"(x)); return y;
}
__device__ __forceinline__ float lg2f(float x) {
    float y; asm("lg2.approx.ftz.f32 %0, %1;" : "=f"(y) : "f"(x)); return y;
}
// 2^k for k <= 0, flushing to 0 below 2^-126
__device__ __forceinline__ float exp2neg(int k) {
    return (k < -126) ? 0.f : __int_as_float((127 + k) << 23);
}

// One block per batch element. Warp 7: warp-synchronous prob-domain CTC DP
// with PER-LANE exponent scales (handles unbounded inter-state dynamic range).
// Warps 0-6: entropy accumulation over the [T,C] slab (float4 streaming).
__global__ void __launch_bounds__(NTHR, 1) ctc_fused(
    const float* __restrict__ lp,      // [T, B, C]
    const int*   __restrict__ targets, // [B, L]
    const int*   __restrict__ in_len,  // [B]
    const int*   __restrict__ tgt_len) // [B]
{
    __shared__ float entsh[7];

    const int b   = blockIdx.x;
    const int tid = threadIdx.x;
    const int w   = tid >> 5;

    if (w < 7) {
        // ---------------- Entropy warps: sum p*log p over full slab ----------
        const int n4 = T_DIM * C_DIM / 4;   // 65536 float4's
        float ent = 0.f;
#pragma unroll 4
        for (int i = tid; i < n4; i += 224) {
            const int t  = i >> 6;          // C/4 = 64
            const int c4 = i & 63;
            const float4 v = __ldg((const float4*)(lp + ((size_t)t * B_DIM + b) * C_DIM) + c4);
            ent = fmaf(ex2f(v.x * LOG2E), v.x, ent);
            ent = fmaf(ex2f(v.y * LOG2E), v.y, ent);
            ent = fmaf(ex2f(v.z * LOG2E), v.z, ent);
            ent = fmaf(ex2f(v.w * LOG2E), v.w, ent);
        }
#pragma unroll
        for (int o = 16; o; o >>= 1) ent += __shfl_xor_sync(~0u, ent, o);
        if ((tid & 31) == 0) entsh[w] = ent;
    } else {
        // ---------------- DP warp: prob-domain CTC forward ------------------
        const int lane = tid & 31;
        const int len  = __ldg(&in_len[b]);
        const int TL   = __ldg(&tgt_len[b]);
        const int tA   = 2 * TL - 1;        // end state (final label)
        const int tB   = 2 * TL;            // end state (final blank)

        // Lane l owns states 4l..4l+3; lane 31 additionally owns state 128.
        const int labA = __ldg(&targets[b * L_DIM + 2 * lane]);       // state 4l+1
        const int labB = __ldg(&targets[b * L_DIM + 2 * lane + 1]);   // state 4l+3
        const int labP = (lane > 0) ? __ldg(&targets[b * L_DIM + 2 * lane - 1]) : -1;
        const float al1 = (lane > 0 && labA != labP) ? 1.f : 0.f;     // skip into 4l+1
        const float al3 = (labB != labA) ? 1.f : 0.f;                 // skip into 4l+3
        const bool  L31 = (lane == 31);

        float a0 = 0.f, a1 = 0.f, a2 = 0.f, a3 = 0.f, a4 = 0.f;
        int   E = 0;                 // per-lane scale: true alpha = stored * 2^E

        const size_t tstr = (size_t)B_DIM * C_DIM;
        const float* base = lp + (size_t)b * C_DIM;

        // Prefetch ring: 3 gather loads per lane per step, depth PF steps.
        float rb[PF], r1[PF], r3[PF];
#pragma unroll
        for (int j = 0; j < PF; ++j) {
            rb[j] = __ldg(base + (size_t)j * tstr);
            r1[j] = __ldg(base + (size_t)j * tstr + labA);
            r3[j] = __ldg(base + (size_t)j * tstr + labB);
        }

        const int lenUp = (len + PF - 1) & ~(PF - 1);   // len<=1024, multiple of PF
        for (int t0 = 0; t0 < lenUp; t0 += PF) {
#pragma unroll
            for (int j = 0; j < PF; ++j) {
                const int t = t0 + j;
                const float pb_ = ex2f(rb[j] * LOG2E);
                const float p1_ = ex2f(r1[j] * LOG2E);
                const float p3_ = ex2f(r3[j] * LOG2E);
                if (t + PF < T_DIM) {
                    rb[j] = __ldg(base + (size_t)(t + PF) * tstr);
                    r1[j] = __ldg(base + (size_t)(t + PF) * tstr + labA);
                    r3[j] = __ldg(base + (size_t)(t + PF) * tstr + labB);
                }

                if (t == 0) {
                    a0 = (lane == 0) ? pb_ : 0.f;
                    a1 = (lane == 0) ? p1_ : 0.f;
                    a2 = 0.f; a3 = 0.f; a4 = 0.f;
                } else {
                    // Cross-lane hand-off with scale reconciliation:
                    // scale the SMALLER-scaled side down to the larger scale.
                    float h3 = __shfl_up_sync(~0u, a3, 1);   // prev lane state 4l-1
                    int   Ep = __shfl_up_sync(~0u, E, 1);
                    if (lane == 0) { h3 = 0.f; Ep = E; }
                    const int d   = Ep - E;                  // >0: neighbor scale larger
                    const float sH = exp2neg(d < 0 ? d : 0); // shrink h3 if we're larger
                    const float sO = exp2neg(d > 0 ? -d : 0);// shrink own if neighbor larger
                    h3 *= sH;
                    a0 *= sO; a1 *= sO; a2 *= sO; a3 *= sO; a4 *= sO;
                    E = (d > 0) ? Ep : E;

                    const float n0 = (a0 + h3) * pb_;                    // blank 4l
                    const float n1 = (fmaf(al1, h3, a0) + a1) * p1_;     // label 4l+1
                    const float n2 = (a2 + a1) * pb_;                    // blank 4l+2
                    const float n3 = (fmaf(al3, a1, a2) + a3) * p3_;     // label 4l+3
                    const float n4 = L31 ? (a4 + a3) * pb_ : 0.f;        // blank 128
                    a0 = n0; a1 = n1; a2 = n2; a3 = n3; a4 = n4;
                }

                if (t == len - 1) {
                    // End mass = alpha[2TL] + alpha[2TL-1]; lanes carry
                    // different scales -> scale-aware warp logsumexp.
                    const int s0 = lane * 4;
                    float pick = 0.f;
                    if (s0     == tB)             pick += a0;   // tB even
                    if (s0 + 1 == tA)             pick += a1;   // tA odd
                    if (s0 + 2 == tB)             pick += a2;
                    if (s0 + 3 == tA)             pick += a3;
                    if (L31 && tB == 128)         pick += a4;
                    float c = (pick > 0.f)
                            ? (lg2f(pick * 0x1p64f) - 64.f + (float)E)
                            : -3.0e38f;
                    float mm = c;
#pragma unroll
                    for (int o = 16; o; o >>= 1)
                        mm = fmaxf(mm, __shfl_xor_sync(~0u, mm, o));
                    float ss = ex2f(c - mm);
#pragma unroll
                    for (int o = 16; o; o >>= 1)
                        ss += __shfl_xor_sync(~0u, ss, o);
                    if (lane == 0) {
                        const float ll2 = mm + lg2f(ss);
                        float nll = -ll2 * LN2;
                        if (!(nll <= 1e29f)) nll = 0.f;  // zero_infinity (+inf/NaN->0)
                        g_nll[b] = nll;
                    }
                }

                if ((t & 1) == 1) {
                    // Per-lane renorm: local max -> exponent ~0. All-zero lanes
                    // take a sentinel scale so they ADOPT the neighbor's scale
                    // on the next hand-off instead of flushing it.
                    float m = fmaxf(fmaxf(a0, a1), fmaxf(a2, a3));
                    m = fmaxf(m, a4);
                    const bool z = (m == 0.f);
                    const int eb = (__float_as_int(m) >> 23) & 255;
                    const int k  = 127 - eb;
                    const float sc = z ? 1.f : __int_as_float((127 + k) << 23); // 2^k
                    a0 *= sc; a1 *= sc; a2 *= sc; a3 *= sc; a4 *= sc;
                    E = z ? ESENT : (E - k);
                }
            }
        }
    }

    __syncthreads();
    if (tid == 0) {
        float s = 0.f;
#pragma unroll
        for (int i = 0; i < 7; ++i) s += entsh[i];
        g_ent[b] = s;   // sum of p*log p (natural log) over this batch's slab
    }
}

__global__ void ctc_finalize(float* __restrict__ out) {
    const int tid = threadIdx.x;  // 32 threads
    float sn = 0.f, se = 0.f;
#pragma unroll
    for (int j = 0; j < 4; ++j) {
        sn += g_nll[tid * 4 + j];
        se += g_ent[tid * 4 + j];
    }
#pragma unroll
    for (int off = 16; off; off >>= 1) {
        sn += __shfl_xor_sync(0xffffffffu, sn, off);
        se += __shfl_xor_sync(0xffffffffu, se, off);
    }
    if (tid == 0) {
        // loss = 0.9 * mean_b(nll) + 0.1 * (sum p*lp) / (T*B)
        out[0] = 0.9f * (sn * (1.0f / (float)B_DIM))
               + 0.1f * (se * (1.0f / ((float)T_DIM * (float)B_DIM)));
    }
}

extern "C" void kernel_launch(void* const* d_in, const int* in_sizes, int n_in,
                              void* d_out, int out_size) {
    const float* lp = (const float*)d_in[0];
    const int*   tg = (const int*)d_in[1];
    const int*   il = (const int*)d_in[2];
    const int*   tl = (const int*)d_in[3];
    (void)in_sizes; (void)n_in; (void)out_size;

    ctc_fused<<<B_DIM, NTHR>>>(lp, tg, il, tl);
    ctc_finalize<<<1, 32>>>((float*)d_out);
}